// round 12
// baseline (speedup 1.0000x reference)
#include <cuda_runtime.h>
#include <math.h>

#define BATCH 1024
#define NTOK  64
#define CDIM  256
#define HEADS 8
#define HDIM  32
#define NWIN  64
#define QKVN  768

// ---------------- scratch (device globals; no allocations) ----------------
__device__ float g_qkv[BATCH * NTOK * QKVN];   // (b*64+t, 768) row-major
__device__ float g_ctx[BATCH * NTOK * CDIM];   // (b*64+t, 256) row-major
__device__ float g_rpb[HEADS * NTOK * NTOK];   // (h, p, q)

// ---------------- relative position bias (MLP + gather + sigmoid) ----------
__global__ __launch_bounds__(256) void rpb_kernel(
    const float* __restrict__ w1, const float* __restrict__ b1,
    const float* __restrict__ w2)
{
    __shared__ float hbt[225][8];
    int tid = threadIdx.x;
    if (tid < 225) {
        int i = tid / 15, j = tid % 15;
        float ri = (float)(i - 7) * (8.0f / 7.0f);
        float rj = (float)(j - 7) * (8.0f / 7.0f);
        float t0 = copysignf(log2f(fabsf(ri) + 1.0f) * (1.0f / 3.0f), ri);
        float t1 = copysignf(log2f(fabsf(rj) + 1.0f) * (1.0f / 3.0f), rj);
        if (ri == 0.0f) t0 = 0.0f;
        if (rj == 0.0f) t1 = 0.0f;
        float acc[8];
        #pragma unroll
        for (int h = 0; h < 8; h++) acc[h] = 0.0f;
        for (int u = 0; u < 512; u++) {
            float hv = fmaxf(t0 * w1[2 * u] + t1 * w1[2 * u + 1] + b1[u], 0.0f);
            #pragma unroll
            for (int h = 0; h < 8; h++) acc[h] += hv * w2[h * 512 + u];
        }
        #pragma unroll
        for (int h = 0; h < 8; h++) hbt[tid][h] = acc[h];
    }
    __syncthreads();
    for (int idx = tid; idx < HEADS * NTOK * NTOK; idx += 256) {
        int h = idx >> 12;
        int p = (idx >> 6) & 63;
        int q = idx & 63;
        int dy = (p >> 3) - (q >> 3) + 7;
        int dx = (p & 7) - (q & 7) + 7;
        float v = hbt[dy * 15 + dx][h];
        g_rpb[idx] = 16.0f / (1.0f + __expf(-v));
    }
}

// -------- fp32x2 SGEMM: C[M,N] = A[M,256]*B[N,256]^T + bias ---------------
// (R11 version — at the measured fp32 FMA-pipe roofline; frozen.)
#define BM 128
#define BN 128
#define BK 16

__device__ __forceinline__ float get_bias(int n, const float* b0,
                                          const float* b1, int mode)
{
    if (mode) return b0[n];
    if (n < 256) return b0[n];
    if (n < 512) return 0.0f;
    return b1[n - 512];
}

__device__ __forceinline__ void sgemm_body(
    const float* __restrict__ A, const float* __restrict__ B,
    float* __restrict__ C, int N,
    const float* __restrict__ bias0, const float* __restrict__ bias1, int mode)
{
    const int K = 256;
    __shared__ float As[BK][BM];
    __shared__ float Bs[BK][BN];
    int tid = threadIdx.x;
    int mBase = blockIdx.y * BM;
    int nBase = blockIdx.x * BN;
    int ty = tid >> 4, tx = tid & 15;

    unsigned long long acc2[4][8];
    #pragma unroll
    for (int i = 0; i < 4; i++)
        #pragma unroll
        for (int j = 0; j < 8; j++) acc2[i][j] = 0ULL;

    for (int kt = 0; kt < K; kt += BK) {
        #pragma unroll
        for (int r = 0; r < 2; r++) {
            int idx = tid + r * 256;
            int row = idx >> 2;
            int k4 = (idx & 3) << 2;
            float4 va = *(const float4*)&A[(size_t)(mBase + row) * K + kt + k4];
            As[k4 + 0][row] = va.x; As[k4 + 1][row] = va.y;
            As[k4 + 2][row] = va.z; As[k4 + 3][row] = va.w;
            float4 vb = *(const float4*)&B[(size_t)(nBase + row) * K + kt + k4];
            Bs[k4 + 0][row] = vb.x; Bs[k4 + 1][row] = vb.y;
            Bs[k4 + 2][row] = vb.z; Bs[k4 + 3][row] = vb.w;
        }
        __syncthreads();
        #pragma unroll
        for (int kk = 0; kk < BK; kk++) {
            unsigned long long a2[4];
            *(ulonglong2*)&a2[0] = *(const ulonglong2*)&As[kk][ty * 8];
            *(ulonglong2*)&a2[2] = *(const ulonglong2*)&As[kk][ty * 8 + 4];
            float b[8];
            *(float4*)&b[0] = *(const float4*)&Bs[kk][tx * 8];
            *(float4*)&b[4] = *(const float4*)&Bs[kk][tx * 8 + 4];
            #pragma unroll
            for (int j = 0; j < 8; j++) {
                unsigned long long b2;
                asm("mov.b64 %0, {%1, %1};" : "=l"(b2) : "f"(b[j]));
                #pragma unroll
                for (int ip = 0; ip < 4; ip++)
                    asm("fma.rn.f32x2 %0, %1, %2, %0;"
                        : "+l"(acc2[ip][j]) : "l"(a2[ip]), "l"(b2));
            }
        }
        __syncthreads();
    }

    #pragma unroll
    for (int ip = 0; ip < 4; ip++) {
        float r0[8], r1[8];
        #pragma unroll
        for (int j = 0; j < 8; j++)
            asm("mov.b64 {%0, %1}, %2;"
                : "=f"(r0[j]), "=f"(r1[j]) : "l"(acc2[ip][j]));
        int m0 = mBase + ty * 8 + 2 * ip;
        #pragma unroll
        for (int jj = 0; jj < 8; jj += 4) {
            int n = nBase + tx * 8 + jj;
            float b0v = get_bias(n + 0, bias0, bias1, mode);
            float b1v = get_bias(n + 1, bias0, bias1, mode);
            float b2v = get_bias(n + 2, bias0, bias1, mode);
            float b3v = get_bias(n + 3, bias0, bias1, mode);
            float4 v0, v1;
            v0.x = r0[jj + 0] + b0v; v0.y = r0[jj + 1] + b1v;
            v0.z = r0[jj + 2] + b2v; v0.w = r0[jj + 3] + b3v;
            v1.x = r1[jj + 0] + b0v; v1.y = r1[jj + 1] + b1v;
            v1.z = r1[jj + 2] + b2v; v1.w = r1[jj + 3] + b3v;
            *(float4*)&C[(size_t)m0 * N + n] = v0;
            *(float4*)&C[(size_t)(m0 + 1) * N + n] = v1;
        }
    }
}

__global__ __launch_bounds__(256) void qkv_gemm_kernel(
    const float* __restrict__ x, const float* __restrict__ w,
    const float* __restrict__ qb, const float* __restrict__ vb)
{
    sgemm_body(x, w, g_qkv, QKVN, qb, vb, 0);
}

__global__ __launch_bounds__(256) void proj_gemm_kernel(
    const float* __restrict__ w, float* __restrict__ out,
    const float* __restrict__ pb)
{
    sgemm_body(g_ctx, w, out, CDIM, pb, nullptr, 1);
}

// ---------------- per-(window,head) attention ------------------------------
__global__ __launch_bounds__(256) void attn_kernel(
    const float* __restrict__ mask, const float* __restrict__ logit_scale)
{
    __shared__ float qs[HDIM][68];     // transposed [d][t]
    __shared__ float ks[HDIM][68];
    __shared__ float vs[NTOK][HDIM];   // [t][d]
    __shared__ float sm[NTOK][65];

    int b = blockIdx.x >> 3;
    int h = blockIdx.x & 7;
    int tid = threadIdx.x;

    #pragma unroll
    for (int r = 0; r < 8; r++) {
        int idx = tid + r * 256;              // 2048 = 64*32
        int t = idx >> 5, d = idx & 31;
        size_t base = (size_t)(b * NTOK + t) * QKVN + h * HDIM + d;
        qs[d][t] = g_qkv[base];
        ks[d][t] = g_qkv[base + CDIM];
        vs[t][d] = g_qkv[base + 2 * CDIM];
    }
    __syncthreads();

    // normalize q,k: 256 threads, 2 per column (16 dims each), shfl combine
    {
        int mat = tid >> 7;            // 0 = q, 1 = k
        int col = (tid >> 1) & 63;
        int half = tid & 1;
        int d0 = half * 16;
        float (*arr)[68] = mat ? ks : qs;
        float ss = 0.0f;
        #pragma unroll
        for (int d = 0; d < 16; d++) {
            float v = arr[d0 + d][col];
            ss += v * v;
        }
        ss += __shfl_xor_sync(0xffffffffu, ss, 1);
        float inv = 1.0f / fmaxf(sqrtf(ss), 1e-12f);
        #pragma unroll
        for (int d = 0; d < 16; d++) arr[d0 + d][col] *= inv;
    }
    __syncthreads();

    float scale = __expf(fminf(logit_scale[h], 4.605170185988091f)); // ln(100)
    int wmask = b & (NWIN - 1);

    {
        int trow = tid >> 4, tcol = tid & 15;
        float s4[4][4];
        #pragma unroll
        for (int i = 0; i < 4; i++)
            #pragma unroll
            for (int j = 0; j < 4; j++) s4[i][j] = 0.0f;
        #pragma unroll
        for (int d = 0; d < HDIM; d++) {
            float4 a = *(const float4*)&qs[d][trow * 4];
            float4 bb = *(const float4*)&ks[d][tcol * 4];
            float av[4] = {a.x, a.y, a.z, a.w};
            float bv[4] = {bb.x, bb.y, bb.z, bb.w};
            #pragma unroll
            for (int i = 0; i < 4; i++)
                #pragma unroll
                for (int j = 0; j < 4; j++) s4[i][j] += av[i] * bv[j];
        }
        #pragma unroll
        for (int i = 0; i < 4; i++) {
            int p = trow * 4 + i;
            float4 rv = *(const float4*)&g_rpb[(h * NTOK + p) * NTOK + tcol * 4];
            float4 mv = *(const float4*)&mask[((size_t)wmask * NTOK + p) * NTOK + tcol * 4];
            sm[p][tcol * 4 + 0] = s4[i][0] * scale + rv.x + mv.x;
            sm[p][tcol * 4 + 1] = s4[i][1] * scale + rv.y + mv.y;
            sm[p][tcol * 4 + 2] = s4[i][2] * scale + rv.z + mv.z;
            sm[p][tcol * 4 + 3] = s4[i][3] * scale + rv.w + mv.w;
        }
    }
    __syncthreads();

    {
        int row = tid >> 2;          // 0..63
        int quad = tid & 3;          // 16 cols each
        int c0 = quad * 16;
        float mx = -1e30f;
        #pragma unroll
        for (int c = 0; c < 16; c++) mx = fmaxf(mx, sm[row][c0 + c]);
        mx = fmaxf(mx, __shfl_xor_sync(0xffffffffu, mx, 1));
        mx = fmaxf(mx, __shfl_xor_sync(0xffffffffu, mx, 2));
        float sum = 0.0f;
        float e[16];
        #pragma unroll
        for (int c = 0; c < 16; c++) {
            e[c] = __expf(sm[row][c0 + c] - mx);
            sum += e[c];
        }
        sum += __shfl_xor_sync(0xffffffffu, sum, 1);
        sum += __shfl_xor_sync(0xffffffffu, sum, 2);
        float inv = 1.0f / sum;
        #pragma unroll
        for (int c = 0; c < 16; c++) sm[row][c0 + c] = e[c] * inv;
    }
    __syncthreads();

    {
        int r2 = tid >> 3;            // 0..31
        int c4 = (tid & 7) * 4;       // 0..28
        float o0[4] = {0.f, 0.f, 0.f, 0.f};
        float o1[4] = {0.f, 0.f, 0.f, 0.f};
        int row0 = r2 * 2;
        #pragma unroll 8
        for (int m = 0; m < NTOK; m++) {
            float s0 = sm[row0][m];
            float s1 = sm[row0 + 1][m];
            float4 vv = *(const float4*)&vs[m][c4];
            o0[0] += s0 * vv.x; o0[1] += s0 * vv.y;
            o0[2] += s0 * vv.z; o0[3] += s0 * vv.w;
            o1[0] += s1 * vv.x; o1[1] += s1 * vv.y;
            o1[2] += s1 * vv.z; o1[3] += s1 * vv.w;
        }
        size_t obase = (size_t)(b * NTOK + row0) * CDIM + h * HDIM + c4;
        *(float4*)&g_ctx[obase] = make_float4(o0[0], o0[1], o0[2], o0[3]);
        *(float4*)&g_ctx[obase + CDIM] = make_float4(o1[0], o1[1], o1[2], o1[3]);
    }
}

// ---------------- entry ----------------------------------------------------
extern "C" void kernel_launch(void* const* d_in, const int* in_sizes, int n_in,
                              void* d_out, int out_size)
{
    (void)in_sizes; (void)n_in; (void)out_size;
    const float* x           = (const float*)d_in[0];
    const float* mask        = (const float*)d_in[1];
    const float* qkv_w       = (const float*)d_in[2];
    const float* q_bias      = (const float*)d_in[3];
    const float* v_bias      = (const float*)d_in[4];
    const float* logit_scale = (const float*)d_in[5];
    const float* mlp_w1      = (const float*)d_in[6];
    const float* mlp_b1      = (const float*)d_in[7];
    const float* mlp_w2      = (const float*)d_in[8];
    const float* proj_w      = (const float*)d_in[9];
    const float* proj_b      = (const float*)d_in[10];
    float* out = (float*)d_out;

    rpb_kernel<<<1, 256>>>(mlp_w1, mlp_b1, mlp_w2);

    dim3 qkv_grid(QKVN / BN, (BATCH * NTOK) / BM);   // (6, 512)
    qkv_gemm_kernel<<<qkv_grid, 256>>>(x, qkv_w, q_bias, v_bias);

    attn_kernel<<<BATCH * HEADS, 256>>>(mask, logit_scale);

    dim3 proj_grid(CDIM / BN, (BATCH * NTOK) / BM);  // (2, 512)
    proj_gemm_kernel<<<proj_grid, 256>>>(proj_w, out, proj_b);
}

// round 13
// speedup vs baseline: 1.0160x; 1.0160x over previous
#include <cuda_runtime.h>
#include <math.h>

#define BATCH 1024
#define NTOK  64
#define CDIM  256
#define HEADS 8
#define HDIM  32
#define NWIN  64
#define QKVN  768

// ---------------- scratch (device globals; no allocations) ----------------
__device__ float g_qkv[BATCH * NTOK * QKVN];   // (b*64+t, 768) row-major
__device__ float g_ctx[BATCH * NTOK * CDIM];   // (b*64+t, 256) row-major
__device__ float g_rpb[HEADS * NTOK * NTOK];   // (h, p, q)

// ---------------- relative position bias (MLP + gather + sigmoid) ----------
__global__ __launch_bounds__(256) void rpb_kernel(
    const float* __restrict__ w1, const float* __restrict__ b1,
    const float* __restrict__ w2)
{
    __shared__ float hbt[225][8];
    int tid = threadIdx.x;
    if (tid < 225) {
        int i = tid / 15, j = tid % 15;
        float ri = (float)(i - 7) * (8.0f / 7.0f);
        float rj = (float)(j - 7) * (8.0f / 7.0f);
        float t0 = copysignf(log2f(fabsf(ri) + 1.0f) * (1.0f / 3.0f), ri);
        float t1 = copysignf(log2f(fabsf(rj) + 1.0f) * (1.0f / 3.0f), rj);
        if (ri == 0.0f) t0 = 0.0f;
        if (rj == 0.0f) t1 = 0.0f;
        float acc[8];
        #pragma unroll
        for (int h = 0; h < 8; h++) acc[h] = 0.0f;
        for (int u = 0; u < 512; u++) {
            float hv = fmaxf(t0 * w1[2 * u] + t1 * w1[2 * u + 1] + b1[u], 0.0f);
            #pragma unroll
            for (int h = 0; h < 8; h++) acc[h] += hv * w2[h * 512 + u];
        }
        #pragma unroll
        for (int h = 0; h < 8; h++) hbt[tid][h] = acc[h];
    }
    __syncthreads();
    for (int idx = tid; idx < HEADS * NTOK * NTOK; idx += 256) {
        int h = idx >> 12;
        int p = (idx >> 6) & 63;
        int q = idx & 63;
        int dy = (p >> 3) - (q >> 3) + 7;
        int dx = (p & 7) - (q & 7) + 7;
        float v = hbt[dy * 15 + dx][h];
        g_rpb[idx] = 16.0f / (1.0f + expf(-v));
    }
}

// -------- fp32x2 SGEMM: C[M,N] = A[M,256]*B[N,256]^T + bias ---------------
// CTA tile 128x64, per-thread 8x4 (packed row-pairs), BK=16.
// Smaller acc -> ~70 regs -> 3 CTAs/SM (24 warps) to cover LDS latency.
#define BM 128
#define BNT 64
#define BK 16

__device__ __forceinline__ float get_bias(int n, const float* b0,
                                          const float* b1, int mode)
{
    if (mode) return b0[n];
    if (n < 256) return b0[n];
    if (n < 512) return 0.0f;
    return b1[n - 512];
}

__device__ __forceinline__ void sgemm_body(
    const float* __restrict__ A, const float* __restrict__ B,
    float* __restrict__ C, int N,
    const float* __restrict__ bias0, const float* __restrict__ bias1, int mode)
{
    const int K = 256;
    __shared__ float As[BK][BM];   // 8 KB
    __shared__ float Bs[BK][BNT];  // 4 KB
    int tid = threadIdx.x;
    int mBase = blockIdx.y * BM;
    int nBase = blockIdx.x * BNT;
    int ty = tid >> 4, tx = tid & 15;   // 16 x 16 threads, 8x4 outputs each

    // packed accumulators: 4 row-pairs x 4 cols
    unsigned long long acc2[4][4];
    #pragma unroll
    for (int i = 0; i < 4; i++)
        #pragma unroll
        for (int j = 0; j < 4; j++) acc2[i][j] = 0ULL;

    // loader coords: A 2 float4/thread, B 1 float4/thread
    int arow0 = tid >> 2;              // 0..63
    int arow1 = arow0 + 64;            // 64..127
    int ak4   = (tid & 3) << 2;
    int brow  = tid >> 2;              // 0..63
    int bk4   = (tid & 3) << 2;

    for (int kt = 0; kt < K; kt += BK) {
        {
            float4 a0 = *(const float4*)&A[(size_t)(mBase + arow0) * K + kt + ak4];
            float4 a1 = *(const float4*)&A[(size_t)(mBase + arow1) * K + kt + ak4];
            float4 vb = *(const float4*)&B[(size_t)(nBase + brow) * K + kt + bk4];
            As[ak4 + 0][arow0] = a0.x; As[ak4 + 1][arow0] = a0.y;
            As[ak4 + 2][arow0] = a0.z; As[ak4 + 3][arow0] = a0.w;
            As[ak4 + 0][arow1] = a1.x; As[ak4 + 1][arow1] = a1.y;
            As[ak4 + 2][arow1] = a1.z; As[ak4 + 3][arow1] = a1.w;
            Bs[bk4 + 0][brow] = vb.x; Bs[bk4 + 1][brow] = vb.y;
            Bs[bk4 + 2][brow] = vb.z; Bs[bk4 + 3][brow] = vb.w;
        }
        __syncthreads();
        #pragma unroll
        for (int kk = 0; kk < BK; kk++) {
            unsigned long long a2[4];
            *(ulonglong2*)&a2[0] = *(const ulonglong2*)&As[kk][ty * 8];
            *(ulonglong2*)&a2[2] = *(const ulonglong2*)&As[kk][ty * 8 + 4];
            float b[4];
            *(float4*)&b[0] = *(const float4*)&Bs[kk][tx * 4];
            #pragma unroll
            for (int j = 0; j < 4; j++) {
                unsigned long long b2;
                asm("mov.b64 %0, {%1, %1};" : "=l"(b2) : "f"(b[j]));
                #pragma unroll
                for (int ip = 0; ip < 4; ip++)
                    asm("fma.rn.f32x2 %0, %1, %2, %0;"
                        : "+l"(acc2[ip][j]) : "l"(a2[ip]), "l"(b2));
            }
        }
        __syncthreads();
    }

    int n = nBase + tx * 4;
    float b0v = get_bias(n + 0, bias0, bias1, mode);
    float b1v = get_bias(n + 1, bias0, bias1, mode);
    float b2v = get_bias(n + 2, bias0, bias1, mode);
    float b3v = get_bias(n + 3, bias0, bias1, mode);
    #pragma unroll
    for (int ip = 0; ip < 4; ip++) {
        float r0[4], r1[4];
        #pragma unroll
        for (int j = 0; j < 4; j++)
            asm("mov.b64 {%0, %1}, %2;"
                : "=f"(r0[j]), "=f"(r1[j]) : "l"(acc2[ip][j]));
        int m0 = mBase + ty * 8 + 2 * ip;
        float4 v0, v1;
        v0.x = r0[0] + b0v; v0.y = r0[1] + b1v;
        v0.z = r0[2] + b2v; v0.w = r0[3] + b3v;
        v1.x = r1[0] + b0v; v1.y = r1[1] + b1v;
        v1.z = r1[2] + b2v; v1.w = r1[3] + b3v;
        *(float4*)&C[(size_t)m0 * N + n] = v0;
        *(float4*)&C[(size_t)(m0 + 1) * N + n] = v1;
    }
}

__global__ __launch_bounds__(256, 3) void qkv_gemm_kernel(
    const float* __restrict__ x, const float* __restrict__ w,
    const float* __restrict__ qb, const float* __restrict__ vb)
{
    sgemm_body(x, w, g_qkv, QKVN, qb, vb, 0);
}

__global__ __launch_bounds__(256, 3) void proj_gemm_kernel(
    const float* __restrict__ w, float* __restrict__ out,
    const float* __restrict__ pb)
{
    sgemm_body(g_ctx, w, out, CDIM, pb, nullptr, 1);
}

// ---------------- per-(window,head) attention (R11 best version) -----------
__global__ __launch_bounds__(256) void attn_kernel(
    const float* __restrict__ mask, const float* __restrict__ logit_scale)
{
    __shared__ float qs[HDIM][68];     // transposed [d][t]
    __shared__ float ks[HDIM][68];
    __shared__ float vs[NTOK][HDIM];   // [t][d]
    __shared__ float sm[NTOK][65];

    int b = blockIdx.x >> 3;
    int h = blockIdx.x & 7;
    int tid = threadIdx.x;

    #pragma unroll
    for (int r = 0; r < 8; r++) {
        int idx = tid + r * 256;              // 2048 = 64*32
        int t = idx >> 5, d = idx & 31;
        size_t base = (size_t)(b * NTOK + t) * QKVN + h * HDIM + d;
        qs[d][t] = g_qkv[base];
        ks[d][t] = g_qkv[base + CDIM];
        vs[t][d] = g_qkv[base + 2 * CDIM];
    }
    __syncthreads();

    if (tid < 128) {
        int t = tid & 63;
        float (*arr)[68] = (tid < 64) ? qs : ks;
        float ss = 0.0f;
        #pragma unroll
        for (int d = 0; d < HDIM; d++) { float v = arr[d][t]; ss += v * v; }
        float inv = 1.0f / fmaxf(sqrtf(ss), 1e-12f);
        #pragma unroll
        for (int d = 0; d < HDIM; d++) arr[d][t] *= inv;
    }
    __syncthreads();

    float scale = expf(fminf(logit_scale[h], 4.605170185988091f)); // ln(100)
    int wmask = b & (NWIN - 1);

    {
        int trow = tid >> 4, tcol = tid & 15;
        float s4[4][4];
        #pragma unroll
        for (int i = 0; i < 4; i++)
            #pragma unroll
            for (int j = 0; j < 4; j++) s4[i][j] = 0.0f;
        #pragma unroll
        for (int d = 0; d < HDIM; d++) {
            float4 a = *(const float4*)&qs[d][trow * 4];
            float4 bb = *(const float4*)&ks[d][tcol * 4];
            float av[4] = {a.x, a.y, a.z, a.w};
            float bv[4] = {bb.x, bb.y, bb.z, bb.w};
            #pragma unroll
            for (int i = 0; i < 4; i++)
                #pragma unroll
                for (int j = 0; j < 4; j++) s4[i][j] += av[i] * bv[j];
        }
        #pragma unroll
        for (int i = 0; i < 4; i++) {
            int p = trow * 4 + i;
            float4 rv = *(const float4*)&g_rpb[(h * NTOK + p) * NTOK + tcol * 4];
            float4 mv = *(const float4*)&mask[((size_t)wmask * NTOK + p) * NTOK + tcol * 4];
            sm[p][tcol * 4 + 0] = s4[i][0] * scale + rv.x + mv.x;
            sm[p][tcol * 4 + 1] = s4[i][1] * scale + rv.y + mv.y;
            sm[p][tcol * 4 + 2] = s4[i][2] * scale + rv.z + mv.z;
            sm[p][tcol * 4 + 3] = s4[i][3] * scale + rv.w + mv.w;
        }
    }
    __syncthreads();

    {
        int row = tid >> 2;          // 0..63
        int quad = tid & 3;          // 16 cols each
        int c0 = quad * 16;
        float mx = -1e30f;
        #pragma unroll
        for (int c = 0; c < 16; c++) mx = fmaxf(mx, sm[row][c0 + c]);
        mx = fmaxf(mx, __shfl_xor_sync(0xffffffffu, mx, 1));
        mx = fmaxf(mx, __shfl_xor_sync(0xffffffffu, mx, 2));
        float sum = 0.0f;
        float e[16];
        #pragma unroll
        for (int c = 0; c < 16; c++) {
            e[c] = expf(sm[row][c0 + c] - mx);
            sum += e[c];
        }
        sum += __shfl_xor_sync(0xffffffffu, sum, 1);
        sum += __shfl_xor_sync(0xffffffffu, sum, 2);
        float inv = 1.0f / sum;
        #pragma unroll
        for (int c = 0; c < 16; c++) sm[row][c0 + c] = e[c] * inv;
    }
    __syncthreads();

    {
        int r2 = tid >> 3;            // 0..31
        int c4 = (tid & 7) * 4;       // 0..28
        float o0[4] = {0.f, 0.f, 0.f, 0.f};
        float o1[4] = {0.f, 0.f, 0.f, 0.f};
        int row0 = r2 * 2;
        #pragma unroll 8
        for (int m = 0; m < NTOK; m++) {
            float s0 = sm[row0][m];
            float s1 = sm[row0 + 1][m];
            float4 vv = *(const float4*)&vs[m][c4];
            o0[0] += s0 * vv.x; o0[1] += s0 * vv.y;
            o0[2] += s0 * vv.z; o0[3] += s0 * vv.w;
            o1[0] += s1 * vv.x; o1[1] += s1 * vv.y;
            o1[2] += s1 * vv.z; o1[3] += s1 * vv.w;
        }
        size_t obase = (size_t)(b * NTOK + row0) * CDIM + h * HDIM + c4;
        *(float4*)&g_ctx[obase] = make_float4(o0[0], o0[1], o0[2], o0[3]);
        *(float4*)&g_ctx[obase + CDIM] = make_float4(o1[0], o1[1], o1[2], o1[3]);
    }
}

// ---------------- entry ----------------------------------------------------
extern "C" void kernel_launch(void* const* d_in, const int* in_sizes, int n_in,
                              void* d_out, int out_size)
{
    (void)in_sizes; (void)n_in; (void)out_size;
    const float* x           = (const float*)d_in[0];
    const float* mask        = (const float*)d_in[1];
    const float* qkv_w       = (const float*)d_in[2];
    const float* q_bias      = (const float*)d_in[3];
    const float* v_bias      = (const float*)d_in[4];
    const float* logit_scale = (const float*)d_in[5];
    const float* mlp_w1      = (const float*)d_in[6];
    const float* mlp_b1      = (const float*)d_in[7];
    const float* mlp_w2      = (const float*)d_in[8];
    const float* proj_w      = (const float*)d_in[9];
    const float* proj_b      = (const float*)d_in[10];
    float* out = (float*)d_out;

    rpb_kernel<<<1, 256>>>(mlp_w1, mlp_b1, mlp_w2);

    dim3 qkv_grid(QKVN / BNT, (BATCH * NTOK) / BM);   // (12, 512)
    qkv_gemm_kernel<<<qkv_grid, 256>>>(x, qkv_w, q_bias, v_bias);

    attn_kernel<<<BATCH * HEADS, 256>>>(mask, logit_scale);

    dim3 proj_grid(CDIM / BNT, (BATCH * NTOK) / BM);  // (4, 512)
    proj_gemm_kernel<<<proj_grid, 256>>>(proj_w, out, proj_b);
}

// round 14
// speedup vs baseline: 1.0400x; 1.0236x over previous
#include <cuda_runtime.h>
#include <math.h>

#define BATCH 1024
#define NTOK  64
#define CDIM  256
#define HEADS 8
#define HDIM  32
#define NWIN  64
#define QKVN  768

// ---------------- scratch (device globals; no allocations) ----------------
__device__ float g_qkv[BATCH * NTOK * QKVN];   // (b*64+t, 768) row-major
__device__ float g_ctx[BATCH * NTOK * CDIM];   // (b*64+t, 256) row-major
__device__ float g_rpb[HEADS * NTOK * NTOK];   // (h, p, q)

// ---------------- relative position bias (MLP + gather + sigmoid) ----------
__global__ __launch_bounds__(256) void rpb_kernel(
    const float* __restrict__ w1, const float* __restrict__ b1,
    const float* __restrict__ w2)
{
    __shared__ float hbt[225][8];
    int tid = threadIdx.x;
    if (tid < 225) {
        int i = tid / 15, j = tid % 15;
        float ri = (float)(i - 7) * (8.0f / 7.0f);
        float rj = (float)(j - 7) * (8.0f / 7.0f);
        float t0 = copysignf(log2f(fabsf(ri) + 1.0f) * (1.0f / 3.0f), ri);
        float t1 = copysignf(log2f(fabsf(rj) + 1.0f) * (1.0f / 3.0f), rj);
        if (ri == 0.0f) t0 = 0.0f;
        if (rj == 0.0f) t1 = 0.0f;
        float acc[8];
        #pragma unroll
        for (int h = 0; h < 8; h++) acc[h] = 0.0f;
        for (int u = 0; u < 512; u++) {
            float hv = fmaxf(t0 * w1[2 * u] + t1 * w1[2 * u + 1] + b1[u], 0.0f);
            #pragma unroll
            for (int h = 0; h < 8; h++) acc[h] += hv * w2[h * 512 + u];
        }
        #pragma unroll
        for (int h = 0; h < 8; h++) hbt[tid][h] = acc[h];
    }
    __syncthreads();
    for (int idx = tid; idx < HEADS * NTOK * NTOK; idx += 256) {
        int h = idx >> 12;
        int p = (idx >> 6) & 63;
        int q = idx & 63;
        int dy = (p >> 3) - (q >> 3) + 7;
        int dx = (p & 7) - (q & 7) + 7;
        float v = hbt[dy * 15 + dx][h];
        g_rpb[idx] = 16.0f / (1.0f + expf(-v));
    }
}

// -------- fp32x2 SGEMM (R13 version — at the fp32 rt=2 roofline; FROZEN) ---
#define BM 128
#define BNT 64
#define BK 16

__device__ __forceinline__ float get_bias(int n, const float* b0,
                                          const float* b1, int mode)
{
    if (mode) return b0[n];
    if (n < 256) return b0[n];
    if (n < 512) return 0.0f;
    return b1[n - 512];
}

__device__ __forceinline__ void sgemm_body(
    const float* __restrict__ A, const float* __restrict__ B,
    float* __restrict__ C, int N,
    const float* __restrict__ bias0, const float* __restrict__ bias1, int mode)
{
    const int K = 256;
    __shared__ float As[BK][BM];   // 8 KB
    __shared__ float Bs[BK][BNT];  // 4 KB
    int tid = threadIdx.x;
    int mBase = blockIdx.y * BM;
    int nBase = blockIdx.x * BNT;
    int ty = tid >> 4, tx = tid & 15;

    unsigned long long acc2[4][4];
    #pragma unroll
    for (int i = 0; i < 4; i++)
        #pragma unroll
        for (int j = 0; j < 4; j++) acc2[i][j] = 0ULL;

    int arow0 = tid >> 2;
    int arow1 = arow0 + 64;
    int ak4   = (tid & 3) << 2;
    int brow  = tid >> 2;
    int bk4   = (tid & 3) << 2;

    for (int kt = 0; kt < K; kt += BK) {
        {
            float4 a0 = *(const float4*)&A[(size_t)(mBase + arow0) * K + kt + ak4];
            float4 a1 = *(const float4*)&A[(size_t)(mBase + arow1) * K + kt + ak4];
            float4 vb = *(const float4*)&B[(size_t)(nBase + brow) * K + kt + bk4];
            As[ak4 + 0][arow0] = a0.x; As[ak4 + 1][arow0] = a0.y;
            As[ak4 + 2][arow0] = a0.z; As[ak4 + 3][arow0] = a0.w;
            As[ak4 + 0][arow1] = a1.x; As[ak4 + 1][arow1] = a1.y;
            As[ak4 + 2][arow1] = a1.z; As[ak4 + 3][arow1] = a1.w;
            Bs[bk4 + 0][brow] = vb.x; Bs[bk4 + 1][brow] = vb.y;
            Bs[bk4 + 2][brow] = vb.z; Bs[bk4 + 3][brow] = vb.w;
        }
        __syncthreads();
        #pragma unroll
        for (int kk = 0; kk < BK; kk++) {
            unsigned long long a2[4];
            *(ulonglong2*)&a2[0] = *(const ulonglong2*)&As[kk][ty * 8];
            *(ulonglong2*)&a2[2] = *(const ulonglong2*)&As[kk][ty * 8 + 4];
            float b[4];
            *(float4*)&b[0] = *(const float4*)&Bs[kk][tx * 4];
            #pragma unroll
            for (int j = 0; j < 4; j++) {
                unsigned long long b2;
                asm("mov.b64 %0, {%1, %1};" : "=l"(b2) : "f"(b[j]));
                #pragma unroll
                for (int ip = 0; ip < 4; ip++)
                    asm("fma.rn.f32x2 %0, %1, %2, %0;"
                        : "+l"(acc2[ip][j]) : "l"(a2[ip]), "l"(b2));
            }
        }
        __syncthreads();
    }

    int n = nBase + tx * 4;
    float b0v = get_bias(n + 0, bias0, bias1, mode);
    float b1v = get_bias(n + 1, bias0, bias1, mode);
    float b2v = get_bias(n + 2, bias0, bias1, mode);
    float b3v = get_bias(n + 3, bias0, bias1, mode);
    #pragma unroll
    for (int ip = 0; ip < 4; ip++) {
        float r0[4], r1[4];
        #pragma unroll
        for (int j = 0; j < 4; j++)
            asm("mov.b64 {%0, %1}, %2;"
                : "=f"(r0[j]), "=f"(r1[j]) : "l"(acc2[ip][j]));
        int m0 = mBase + ty * 8 + 2 * ip;
        float4 v0, v1;
        v0.x = r0[0] + b0v; v0.y = r0[1] + b1v;
        v0.z = r0[2] + b2v; v0.w = r0[3] + b3v;
        v1.x = r1[0] + b0v; v1.y = r1[1] + b1v;
        v1.z = r1[2] + b2v; v1.w = r1[3] + b3v;
        *(float4*)&C[(size_t)m0 * N + n] = v0;
        *(float4*)&C[(size_t)(m0 + 1) * N + n] = v1;
    }
}

__global__ __launch_bounds__(256, 3) void qkv_gemm_kernel(
    const float* __restrict__ x, const float* __restrict__ w,
    const float* __restrict__ qb, const float* __restrict__ vb)
{
    sgemm_body(x, w, g_qkv, QKVN, qb, vb, 0);
}

__global__ __launch_bounds__(256, 3) void proj_gemm_kernel(
    const float* __restrict__ w, float* __restrict__ out,
    const float* __restrict__ pb)
{
    sgemm_body(g_ctx, w, out, CDIM, pb, nullptr, 1);
}

// ---------------- per-(window,head) attention — LSU-optimized --------------
__global__ __launch_bounds__(256) void attn_kernel(
    const float* __restrict__ mask, const float* __restrict__ logit_scale)
{
    __shared__ float qs[HDIM][68];     // transposed [d][t] (stride 272B, 16B-aligned)
    __shared__ float ks[HDIM][68];
    __shared__ float vs[NTOK][HDIM];   // [t][d]
    __shared__ float sm[NTOK][68];     // stride 272B, 16B-aligned rows

    int b = blockIdx.x >> 3;
    int h = blockIdx.x & 7;
    int tid = threadIdx.x;

    // float4 global loads: 512 float4 per matrix, 2 per thread
    #pragma unroll
    for (int r = 0; r < 2; r++) {
        int idx = tid + r * 256;              // 0..511
        int t = idx >> 3, d4 = (idx & 7) << 2;
        size_t base = (size_t)(b * NTOK + t) * QKVN + h * HDIM + d4;
        float4 qv = *(const float4*)&g_qkv[base];
        float4 kv = *(const float4*)&g_qkv[base + CDIM];
        float4 vv = *(const float4*)&g_qkv[base + 2 * CDIM];
        qs[d4 + 0][t] = qv.x; qs[d4 + 1][t] = qv.y;
        qs[d4 + 2][t] = qv.z; qs[d4 + 3][t] = qv.w;
        ks[d4 + 0][t] = kv.x; ks[d4 + 1][t] = kv.y;
        ks[d4 + 2][t] = kv.z; ks[d4 + 3][t] = kv.w;
        *(float4*)&vs[t][d4] = vv;
    }
    __syncthreads();

    // normalize q,k (proven R11 version)
    if (tid < 128) {
        int t = tid & 63;
        float (*arr)[68] = (tid < 64) ? qs : ks;
        float ss = 0.0f;
        #pragma unroll
        for (int d = 0; d < HDIM; d++) { float v = arr[d][t]; ss += v * v; }
        float inv = 1.0f / fmaxf(sqrtf(ss), 1e-12f);
        #pragma unroll
        for (int d = 0; d < HDIM; d++) arr[d][t] *= inv;
    }
    __syncthreads();

    float scale = expf(fminf(logit_scale[h], 4.605170185988091f)); // ln(100)
    int wmask = b & (NWIN - 1);

    // S = qn @ kn^T (unchanged — already wavefront-efficient)
    {
        int trow = tid >> 4, tcol = tid & 15;
        float s4[4][4];
        #pragma unroll
        for (int i = 0; i < 4; i++)
            #pragma unroll
            for (int j = 0; j < 4; j++) s4[i][j] = 0.0f;
        #pragma unroll
        for (int d = 0; d < HDIM; d++) {
            float4 a = *(const float4*)&qs[d][trow * 4];
            float4 bb = *(const float4*)&ks[d][tcol * 4];
            float av[4] = {a.x, a.y, a.z, a.w};
            float bv[4] = {bb.x, bb.y, bb.z, bb.w};
            #pragma unroll
            for (int i = 0; i < 4; i++)
                #pragma unroll
                for (int j = 0; j < 4; j++) s4[i][j] += av[i] * bv[j];
        }
        #pragma unroll
        for (int i = 0; i < 4; i++) {
            int p = trow * 4 + i;
            float4 rv = *(const float4*)&g_rpb[(h * NTOK + p) * NTOK + tcol * 4];
            float4 mv = *(const float4*)&mask[((size_t)wmask * NTOK + p) * NTOK + tcol * 4];
            sm[p][tcol * 4 + 0] = s4[i][0] * scale + rv.x + mv.x;
            sm[p][tcol * 4 + 1] = s4[i][1] * scale + rv.y + mv.y;
            sm[p][tcol * 4 + 2] = s4[i][2] * scale + rv.z + mv.z;
            sm[p][tcol * 4 + 3] = s4[i][3] * scale + rv.w + mv.w;
        }
    }
    __syncthreads();

    // softmax: quad per row, float4 smem traffic
    {
        int row = tid >> 2;
        int c0 = (tid & 3) * 16;
        float4 x0 = *(const float4*)&sm[row][c0];
        float4 x1 = *(const float4*)&sm[row][c0 + 4];
        float4 x2 = *(const float4*)&sm[row][c0 + 8];
        float4 x3 = *(const float4*)&sm[row][c0 + 12];
        float mx = fmaxf(fmaxf(fmaxf(x0.x, x0.y), fmaxf(x0.z, x0.w)),
                         fmaxf(fmaxf(x1.x, x1.y), fmaxf(x1.z, x1.w)));
        mx = fmaxf(mx, fmaxf(fmaxf(fmaxf(x2.x, x2.y), fmaxf(x2.z, x2.w)),
                             fmaxf(fmaxf(x3.x, x3.y), fmaxf(x3.z, x3.w))));
        mx = fmaxf(mx, __shfl_xor_sync(0xffffffffu, mx, 1));
        mx = fmaxf(mx, __shfl_xor_sync(0xffffffffu, mx, 2));
        x0.x = expf(x0.x - mx); x0.y = expf(x0.y - mx);
        x0.z = expf(x0.z - mx); x0.w = expf(x0.w - mx);
        x1.x = expf(x1.x - mx); x1.y = expf(x1.y - mx);
        x1.z = expf(x1.z - mx); x1.w = expf(x1.w - mx);
        x2.x = expf(x2.x - mx); x2.y = expf(x2.y - mx);
        x2.z = expf(x2.z - mx); x2.w = expf(x2.w - mx);
        x3.x = expf(x3.x - mx); x3.y = expf(x3.y - mx);
        x3.z = expf(x3.z - mx); x3.w = expf(x3.w - mx);
        float sum = (x0.x + x0.y + x0.z + x0.w) + (x1.x + x1.y + x1.z + x1.w)
                  + (x2.x + x2.y + x2.z + x2.w) + (x3.x + x3.y + x3.z + x3.w);
        sum += __shfl_xor_sync(0xffffffffu, sum, 1);
        sum += __shfl_xor_sync(0xffffffffu, sum, 2);
        float inv = 1.0f / sum;
        x0.x *= inv; x0.y *= inv; x0.z *= inv; x0.w *= inv;
        x1.x *= inv; x1.y *= inv; x1.z *= inv; x1.w *= inv;
        x2.x *= inv; x2.y *= inv; x2.z *= inv; x2.w *= inv;
        x3.x *= inv; x3.y *= inv; x3.z *= inv; x3.w *= inv;
        *(float4*)&sm[row][c0] = x0;
        *(float4*)&sm[row][c0 + 4] = x1;
        *(float4*)&sm[row][c0 + 8] = x2;
        *(float4*)&sm[row][c0 + 12] = x3;
    }
    __syncthreads();

    // O = S @ V : vectorized over m (4 m-values per iteration)
    {
        int r2 = tid >> 3;            // 0..31 -> rows 2*r2, 2*r2+1
        int c4 = (tid & 7) * 4;       // 0..28
        int row0 = r2 * 2;
        float o0[4] = {0.f, 0.f, 0.f, 0.f};
        float o1[4] = {0.f, 0.f, 0.f, 0.f};
        #pragma unroll 4
        for (int m = 0; m < NTOK; m += 4) {
            float4 s0 = *(const float4*)&sm[row0][m];
            float4 s1 = *(const float4*)&sm[row0 + 1][m];
            float4 va = *(const float4*)&vs[m + 0][c4];
            float4 vb = *(const float4*)&vs[m + 1][c4];
            float4 vc = *(const float4*)&vs[m + 2][c4];
            float4 vd = *(const float4*)&vs[m + 3][c4];
            o0[0] += s0.x * va.x + s0.y * vb.x + s0.z * vc.x + s0.w * vd.x;
            o0[1] += s0.x * va.y + s0.y * vb.y + s0.z * vc.y + s0.w * vd.y;
            o0[2] += s0.x * va.z + s0.y * vb.z + s0.z * vc.z + s0.w * vd.z;
            o0[3] += s0.x * va.w + s0.y * vb.w + s0.z * vc.w + s0.w * vd.w;
            o1[0] += s1.x * va.x + s1.y * vb.x + s1.z * vc.x + s1.w * vd.x;
            o1[1] += s1.x * va.y + s1.y * vb.y + s1.z * vc.y + s1.w * vd.y;
            o1[2] += s1.x * va.z + s1.y * vb.z + s1.z * vc.z + s1.w * vd.z;
            o1[3] += s1.x * va.w + s1.y * vb.w + s1.z * vc.w + s1.w * vd.w;
        }
        size_t obase = (size_t)(b * NTOK + row0) * CDIM + h * HDIM + c4;
        *(float4*)&g_ctx[obase] = make_float4(o0[0], o0[1], o0[2], o0[3]);
        *(float4*)&g_ctx[obase + CDIM] = make_float4(o1[0], o1[1], o1[2], o1[3]);
    }
}

// ---------------- entry ----------------------------------------------------
extern "C" void kernel_launch(void* const* d_in, const int* in_sizes, int n_in,
                              void* d_out, int out_size)
{
    (void)in_sizes; (void)n_in; (void)out_size;
    const float* x           = (const float*)d_in[0];
    const float* mask        = (const float*)d_in[1];
    const float* qkv_w       = (const float*)d_in[2];
    const float* q_bias      = (const float*)d_in[3];
    const float* v_bias      = (const float*)d_in[4];
    const float* logit_scale = (const float*)d_in[5];
    const float* mlp_w1      = (const float*)d_in[6];
    const float* mlp_b1      = (const float*)d_in[7];
    const float* mlp_w2      = (const float*)d_in[8];
    const float* proj_w      = (const float*)d_in[9];
    const float* proj_b      = (const float*)d_in[10];
    float* out = (float*)d_out;

    rpb_kernel<<<1, 256>>>(mlp_w1, mlp_b1, mlp_w2);

    dim3 qkv_grid(QKVN / BNT, (BATCH * NTOK) / BM);   // (12, 512)
    qkv_gemm_kernel<<<qkv_grid, 256>>>(x, qkv_w, q_bias, v_bias);

    attn_kernel<<<BATCH * HEADS, 256>>>(mask, logit_scale);

    dim3 proj_grid(CDIM / BNT, (BATCH * NTOK) / BM);  // (4, 512)
    proj_gemm_kernel<<<proj_grid, 256>>>(proj_w, out, proj_b);
}